// round 15
// baseline (speedup 1.0000x reference)
#include <cuda_runtime.h>
#include <cuda_bf16.h>
#include <cstdint>
#include <math.h>

// Normalized embeddings scratch (bf16): 8192 * 256 * 2B = 4 MB, L2-resident.
__device__ __nv_bfloat16 g_en[8192 * 256];

// ---------------------------------------------------------------------------
// Kernel 1: row-normalize embeddings (fp32 -> bf16). One warp per row, D=256.
// Also zeroes the (poisoned) output scalar from block 0.
// ---------------------------------------------------------------------------
__global__ void normalize_kernel(const float* __restrict__ emb, int B,
                                 float* __restrict__ out) {
    if (blockIdx.x == 0 && threadIdx.x == 0) out[0] = 0.0f;

    const int warpId = threadIdx.x >> 5;
    const int lane   = threadIdx.x & 31;
    const int row    = blockIdx.x * 8 + warpId;
    if (row >= B) return;

    const float4* p = reinterpret_cast<const float4*>(emb + (size_t)row * 256);
    float4 v0 = p[lane];
    float4 v1 = p[lane + 32];

    float ss = v0.x * v0.x + v0.y * v0.y + v0.z * v0.z + v0.w * v0.w
             + v1.x * v1.x + v1.y * v1.y + v1.z * v1.z + v1.w * v1.w;
    #pragma unroll
    for (int o = 16; o > 0; o >>= 1) ss += __shfl_xor_sync(0xffffffffu, ss, o);

    const float scale = 1.0f / fmaxf(sqrtf(ss), 1e-8f);

    __nv_bfloat162 a0 = __floats2bfloat162_rn(v0.x * scale, v0.y * scale);
    __nv_bfloat162 a1 = __floats2bfloat162_rn(v0.z * scale, v0.w * scale);
    __nv_bfloat162 b0 = __floats2bfloat162_rn(v1.x * scale, v1.y * scale);
    __nv_bfloat162 b1 = __floats2bfloat162_rn(v1.z * scale, v1.w * scale);

    uint2 ua, ub;
    ua.x = *reinterpret_cast<unsigned*>(&a0);
    ua.y = *reinterpret_cast<unsigned*>(&a1);
    ub.x = *reinterpret_cast<unsigned*>(&b0);
    ub.y = *reinterpret_cast<unsigned*>(&b1);

    uint2* orow = reinterpret_cast<uint2*>(g_en + (size_t)row * 256);
    orow[lane]      = ua;
    orow[lane + 32] = ub;
}

// ---------------------------------------------------------------------------
// Kernel 2: fused cos-GEMM tile + |text - cos| masked reduction.
// DEEP barrier-free pipeline at 2 CTAs/SM:
//   - 6 uniform 16 KB slots. K=256 as EIGHT K=32 chunks (A 8 KB + B 8 KB per
//     chunk-slot); text as FOUR 32-row quarters (16 KB each).
//   - ring: ch0..5 -> s0..5 (prologue, 96 KB in flight), ch6->s0, ch7->s1,
//     textq0..3 -> s2..s5 (each after that slot's empty barrier).
//   - full[] barriers: cp.async.mbarrier.arrive.noinc; empty[]: plain arrive
//     after each thread's last read. All waits per-thread try_wait -> warps
//     free-run; NO __syncthreads between first MMA and the final reduction.
//   - epilogue warp with row-strip wr waits only on its own text quarter.
// Operand swizzle for 64 B rows: chunk ^ ((row>>1)&3) -> 8 rows, 8 distinct
// bank phases. Text swizzle: chunk ^ (row&7) on 512 B rows (as R14).
// smem = 6 x 16384 = 98304 -> 2 CTAs/SM (16 warps).
// ---------------------------------------------------------------------------
#define SLOT_B   16384
#define STRIP    8192                      // A strip size within an op slot
#define SMEM_TOTAL (6 * SLOT_B)            // 98304

#define LDSM4(R0, R1, R2, R3, ADDR)                                          \
    asm volatile("ldmatrix.sync.aligned.m8n8.x4.shared.b16 {%0,%1,%2,%3}, [%4];" \
                 : "=r"(R0), "=r"(R1), "=r"(R2), "=r"(R3) : "r"(ADDR))

#define MMA16816(C, A, B0, B1)                                               \
    asm volatile("mma.sync.aligned.m16n8k16.row.col.f32.bf16.bf16.f32 "      \
                 "{%0,%1,%2,%3}, {%4,%5,%6,%7}, {%8,%9}, {%0,%1,%2,%3};"     \
                 : "+f"((C)[0]), "+f"((C)[1]), "+f"((C)[2]), "+f"((C)[3])    \
                 : "r"((A)[0]), "r"((A)[1]), "r"((A)[2]), "r"((A)[3]),       \
                   "r"(B0), "r"(B1))

#define CP16(S, G)                                                           \
    asm volatile("cp.async.cg.shared.global [%0], [%1], 16;"                 \
                 :: "r"(S), "l"(G) : "memory")

#define ARRIVE_NOINC(MBAR)                                                   \
    asm volatile("cp.async.mbarrier.arrive.noinc.shared::cta.b64 [%0];"      \
                 :: "r"(MBAR) : "memory")

#define ARRIVE(MBAR)                                                         \
    asm volatile("mbarrier.arrive.shared::cta.b64 _, [%0];"                  \
                 :: "r"(MBAR) : "memory")

#define MBAR_WAIT_P0(MBAR) do {                                              \
    uint32_t _done;                                                          \
    asm volatile("{\n\t.reg .pred p;\n\t"                                    \
                 "mbarrier.try_wait.parity.acquire.cta.shared::cta.b64 p, [%1], 0;\n\t" \
                 "selp.b32 %0, 1, 0, p;\n\t}"                                \
                 : "=r"(_done) : "r"(MBAR) : "memory");                      \
    if (!_done) {                                                            \
        asm volatile("{\n\t.reg .pred P1;\n\t"                               \
                     "W%=:\n\t"                                              \
                     "mbarrier.try_wait.parity.acquire.cta.shared::cta.b64 P1, [%0], 0, 0x989680;\n\t" \
                     "@P1 bra.uni D%=;\n\t"                                  \
                     "bra.uni W%=;\n\t"                                      \
                     "D%=:\n\t}" :: "r"(MBAR) : "memory");                   \
    }                                                                        \
} while (0)

// Stage one K=32 operand chunk (A + B, swizzled 64 B rows) into a 16 KB slot.
__device__ __forceinline__ void stage_op(uint32_t slot, int ch,
                                         const char* Ag, const char* Bg,
                                         int tid) {
    #pragma unroll
    for (int i = tid; i < 512; i += 256) {           // 128 rows x 4 x 16B
        const int r = i >> 2;
        const int c = i & 3;
        const uint32_t soff = (uint32_t)r * 64
                            + (uint32_t)((c ^ ((r >> 1) & 3)) << 4);
        const size_t   goff = (size_t)r * 512 + (size_t)ch * 64 + (size_t)c * 16;
        CP16(slot + soff, Ag + goff);
        CP16(slot + STRIP + soff, Bg + goff);
    }
}

// Stage 32 text rows (512 B each, swizzled) into a 16 KB slot.
__device__ __forceinline__ void stage_text(uint32_t slot, const char* tg,
                                           int B, int tid) {
    #pragma unroll
    for (int i = tid; i < 1024; i += 256) {          // 32 rows x 32 x 16B
        const int r = i >> 5;
        const int c = i & 31;
        const uint32_t soff = (uint32_t)r * 512 + (uint32_t)((c ^ (r & 7)) << 4);
        CP16(slot + soff, tg + (size_t)r * B * 4 + (size_t)c * 16);
    }
}

// One K=32 chunk of MMAs (2 k16 steps) from the given slot.
__device__ __forceinline__ void mma_chunk(uint32_t slot, uint32_t aRow,
                                          uint32_t bRow, uint32_t aHi,
                                          uint32_t bHi, uint32_t aKey,
                                          uint32_t bKey, float c[2][8][4]) {
    #pragma unroll
    for (int kc = 0; kc < 2; kc++) {
        uint32_t a[2][4];
        #pragma unroll
        for (int mt = 0; mt < 2; mt++)
            LDSM4(a[mt][0], a[mt][1], a[mt][2], a[mt][3],
                  slot + aRow + (uint32_t)(mt * 1024)
                       + (uint32_t)((((kc * 2) + aHi) ^ aKey) << 4));
        uint32_t b[4][4];
        #pragma unroll
        for (int p = 0; p < 4; p++)
            LDSM4(b[p][0], b[p][1], b[p][2], b[p][3],
                  slot + STRIP + bRow + (uint32_t)(p * 1024)
                       + (uint32_t)((((kc * 2) + bHi) ^ bKey) << 4));
        #pragma unroll
        for (int mt = 0; mt < 2; mt++)
            #pragma unroll
            for (int nt = 0; nt < 8; nt++)
                MMA16816(c[mt][nt], a[mt],
                         b[nt >> 1][(nt & 1) * 2], b[nt >> 1][(nt & 1) * 2 + 1]);
    }
}

__global__ __launch_bounds__(256, 2)
void loss_kernel(const float* __restrict__ text, float* __restrict__ out,
                 int B, float scale) {
    extern __shared__ char smem[];
    uint32_t sbase;
    asm("{ .reg .u64 t; cvta.to.shared.u64 t, %1; cvt.u32.u64 %0, t; }"
        : "=r"(sbase) : "l"((const void*)smem));

    __shared__ __align__(8) uint64_t mbars[18];  // FB0..11, EB0..5
    __shared__ float red[8];
    uint32_t mb0;
    asm("{ .reg .u64 t; cvta.to.shared.u64 t, %1; cvt.u32.u64 %0, t; }"
        : "=r"(mb0) : "l"((const void*)mbars));
    #define FB(i) (mb0 + (i) * 8)           // full barrier, stage order
    #define EB(i) (mb0 + 96 + (i) * 8)      // empty barrier for slot i

    const int tid = threadIdx.x;

    // ---- linear block id -> upper-triangular (by, bx), by <= bx ----
    const int NT = B >> 7;
    int t = blockIdx.x;
    int by = 0;
    while (t >= NT - by) { t -= NT - by; ++by; }
    const int bx = by + t;

    const char* __restrict__ Ag =
        reinterpret_cast<const char*>(g_en + (size_t)by * 32768);
    const char* __restrict__ Bg =
        reinterpret_cast<const char*>(g_en + (size_t)bx * 32768);
    const char* __restrict__ tg = reinterpret_cast<const char*>(
        text + (size_t)(by * 128) * B + (size_t)bx * 128);

    // ---- init barriers (all expect 256 arrivals) ----
    if (tid == 0) {
        #pragma unroll
        for (int m = 0; m < 18; m++)
            asm volatile("mbarrier.init.shared.b64 [%0], %1;"
                         :: "r"(mb0 + m * 8), "r"(256u) : "memory");
    }
    __syncthreads();   // init visible before any arrive

    uint32_t S[6];
    #pragma unroll
    for (int i = 0; i < 6; i++) S[i] = sbase + (uint32_t)i * SLOT_B;

    // ---- prologue: 6 chunks (96 KB) in flight ----
    #pragma unroll
    for (int ch = 0; ch < 6; ch++) {
        stage_op(S[ch], ch, Ag, Bg, tid);
        ARRIVE_NOINC(FB(ch));
    }

    // ---- warp / fragment geometry ----
    const int warpId = tid >> 5;
    const int lane   = tid & 31;
    const int wr = warpId & 3;    // 32-row strip
    const int wc = warpId >> 2;   // 64-col strip
    const int grp = lane >> 3;

    const uint32_t aRow = (uint32_t)((wr * 32 + (lane & 15)) * 64);
    const uint32_t bRow = (uint32_t)((wc * 64 + (grp >> 1) * 8 + (lane & 7)) * 64);
    const uint32_t aHi  = (uint32_t)(lane >> 4);
    const uint32_t bHi  = (uint32_t)(grp & 1);
    const uint32_t aKey = (uint32_t)(((lane & 15) >> 1) & 3);
    const uint32_t bKey = (uint32_t)(((lane & 7) >> 1) & 3);

    float c[2][8][4];
    #pragma unroll
    for (int mt = 0; mt < 2; mt++)
        #pragma unroll
        for (int nt = 0; nt < 8; nt++)
            #pragma unroll
            for (int e = 0; e < 4; e++) c[mt][nt][e] = 0.0f;

    // ---- free-running deep pipeline (no __syncthreads until reduction) ----
    MBAR_WAIT_P0(FB(0)); mma_chunk(S[0], aRow, bRow, aHi, bHi, aKey, bKey, c); ARRIVE(EB(0));
    MBAR_WAIT_P0(FB(1)); mma_chunk(S[1], aRow, bRow, aHi, bHi, aKey, bKey, c); ARRIVE(EB(1));

    MBAR_WAIT_P0(EB(0)); stage_op(S[0], 6, Ag, Bg, tid); ARRIVE_NOINC(FB(6));

    MBAR_WAIT_P0(FB(2)); mma_chunk(S[2], aRow, bRow, aHi, bHi, aKey, bKey, c); ARRIVE(EB(2));

    MBAR_WAIT_P0(EB(1)); stage_op(S[1], 7, Ag, Bg, tid); ARRIVE_NOINC(FB(7));

    MBAR_WAIT_P0(FB(3)); mma_chunk(S[3], aRow, bRow, aHi, bHi, aKey, bKey, c); ARRIVE(EB(3));

    MBAR_WAIT_P0(EB(2)); stage_text(S[2], tg, B, tid); ARRIVE_NOINC(FB(8));

    MBAR_WAIT_P0(FB(4)); mma_chunk(S[4], aRow, bRow, aHi, bHi, aKey, bKey, c); ARRIVE(EB(4));

    MBAR_WAIT_P0(EB(3)); stage_text(S[3], tg + (size_t)32 * B * 4, B, tid); ARRIVE_NOINC(FB(9));

    MBAR_WAIT_P0(FB(5)); mma_chunk(S[5], aRow, bRow, aHi, bHi, aKey, bKey, c); ARRIVE(EB(5));

    MBAR_WAIT_P0(EB(4)); stage_text(S[4], tg + (size_t)64 * B * 4, B, tid); ARRIVE_NOINC(FB(10));

    MBAR_WAIT_P0(FB(6)); mma_chunk(S[0], aRow, bRow, aHi, bHi, aKey, bKey, c);

    MBAR_WAIT_P0(EB(5)); stage_text(S[5], tg + (size_t)96 * B * 4, B, tid); ARRIVE_NOINC(FB(11));

    MBAR_WAIT_P0(FB(7)); mma_chunk(S[1], aRow, bRow, aHi, bHi, aKey, bKey, c);

    // ---- epilogue: wait only on THIS warp's text quarter (rows wr*32..) ----
    MBAR_WAIT_P0(FB(8 + wr));

    const int qrow = lane >> 2;          // 0..7
    const int qcol = (lane & 3) * 2;     // 0,2,4,6
    const bool diag = (bx == by);
    const char* __restrict__ Tb = smem + (size_t)(2 + wr) * SLOT_B;

    float acc = 0.0f;
    #pragma unroll
    for (int mt = 0; mt < 2; mt++) {
        const int r0 = wr * 32 + mt * 16 + qrow;        // tile rows r0, r0+8
        const int lr = r0 & 31;                          // row within quarter
        #pragma unroll
        for (int nt = 0; nt < 8; nt++) {
            const int cc = wc * 64 + nt * 8 + qcol;
            const uint32_t chunk = (uint32_t)(cc >> 2);
            const uint32_t off = (uint32_t)lr * 512
                               + ((chunk ^ (uint32_t)qrow) << 4)
                               + (uint32_t)((cc & 3) * 4);
            const float2 t0 = *reinterpret_cast<const float2*>(Tb + off);
            const float2 t1 = *reinterpret_cast<const float2*>(Tb + off + 4096);
            const float* cf = c[mt][nt];
            if (!diag) {
                acc += fabsf(t0.x - cf[0]) + fabsf(t0.y - cf[1])
                     + fabsf(t1.x - cf[2]) + fabsf(t1.y - cf[3]);
            } else {
                if (cc     > r0)     acc += fabsf(t0.x - cf[0]);
                if (cc + 1 > r0)     acc += fabsf(t0.y - cf[1]);
                if (cc     > r0 + 8) acc += fabsf(t1.x - cf[2]);
                if (cc + 1 > r0 + 8) acc += fabsf(t1.y - cf[3]);
            }
        }
    }

    // ---- reduction: warp shuffle -> smem -> one atomicAdd ----
    #pragma unroll
    for (int o = 16; o > 0; o >>= 1) acc += __shfl_xor_sync(0xffffffffu, acc, o);
    if (lane == 0) red[warpId] = acc;
    __syncthreads();
    if (tid == 0) {
        float s = 0.0f;
        #pragma unroll
        for (int w = 0; w < 8; w++) s += red[w];
        atomicAdd(out, s * scale);
    }
}

// ---------------------------------------------------------------------------
// Launch
// ---------------------------------------------------------------------------
extern "C" void kernel_launch(void* const* d_in, const int* in_sizes, int n_in,
                              void* d_out, int out_size) {
    const float* emb  = (const float*)d_in[0];   // [B, D] fp32
    const float* text = (const float*)d_in[1];   // [B, B] fp32
    float* out = (float*)d_out;

    const int B = (int)(sqrt((double)in_sizes[1]) + 0.5);   // 8192
    const double count = (double)B * (double)(B - 1) / 2.0;
    const float scale = (float)(0.1 / count);

    cudaFuncSetAttribute(loss_kernel,
                         cudaFuncAttributeMaxDynamicSharedMemorySize, SMEM_TOTAL);

    normalize_kernel<<<B / 8, 256>>>(emb, B, out);

    const int NT = B / 128;
    const int nblocks = NT * (NT + 1) / 2;   // 2080 upper-tri tiles
    loss_kernel<<<nblocks, 256, SMEM_TOTAL>>>(text, out, B, scale);
}

// round 16
// speedup vs baseline: 1.3180x; 1.3180x over previous
#include <cuda_runtime.h>
#include <cuda_bf16.h>
#include <cstdint>
#include <math.h>

// Normalized embeddings scratch (bf16): 8192 * 256 * 2B = 4 MB, L2-resident.
__device__ __nv_bfloat16 g_en[8192 * 256];

// ---------------------------------------------------------------------------
// Kernel 1: row-normalize embeddings (fp32 -> bf16). One warp per row, D=256.
// Also zeroes the (poisoned) output scalar from block 0.
// ---------------------------------------------------------------------------
__global__ void normalize_kernel(const float* __restrict__ emb, int B,
                                 float* __restrict__ out) {
    if (blockIdx.x == 0 && threadIdx.x == 0) out[0] = 0.0f;

    const int warpId = threadIdx.x >> 5;
    const int lane   = threadIdx.x & 31;
    const int row    = blockIdx.x * 8 + warpId;
    if (row >= B) return;

    const float4* p = reinterpret_cast<const float4*>(emb + (size_t)row * 256);
    float4 v0 = p[lane];
    float4 v1 = p[lane + 32];

    float ss = v0.x * v0.x + v0.y * v0.y + v0.z * v0.z + v0.w * v0.w
             + v1.x * v1.x + v1.y * v1.y + v1.z * v1.z + v1.w * v1.w;
    #pragma unroll
    for (int o = 16; o > 0; o >>= 1) ss += __shfl_xor_sync(0xffffffffu, ss, o);

    const float scale = 1.0f / fmaxf(sqrtf(ss), 1e-8f);

    __nv_bfloat162 a0 = __floats2bfloat162_rn(v0.x * scale, v0.y * scale);
    __nv_bfloat162 a1 = __floats2bfloat162_rn(v0.z * scale, v0.w * scale);
    __nv_bfloat162 b0 = __floats2bfloat162_rn(v1.x * scale, v1.y * scale);
    __nv_bfloat162 b1 = __floats2bfloat162_rn(v1.z * scale, v1.w * scale);

    uint2 ua, ub;
    ua.x = *reinterpret_cast<unsigned*>(&a0);
    ua.y = *reinterpret_cast<unsigned*>(&a1);
    ub.x = *reinterpret_cast<unsigned*>(&b0);
    ub.y = *reinterpret_cast<unsigned*>(&b1);

    uint2* orow = reinterpret_cast<uint2*>(g_en + (size_t)row * 256);
    orow[lane]      = ua;
    orow[lane + 32] = ub;
}

// ---------------------------------------------------------------------------
// Kernel 2: fused cos-GEMM tile + |text - cos| masked reduction.
// Barrier-free pipeline (R14 base) + dedicated T0 text slot + quarter-granular
// epilogue gating:
//   - 3 op slots x 32 KB (XOR swizzle): ch0->s0, ch1->s1, ch2->s2, ch3->s0.
//   - text quarters (16 KB, 32 rows each): q0->T0 staged in the PROLOGUE
//     (DRAM latency hidden under the whole mainloop), q1->s1 and q3->s1+16K
//     (after EB1), q2->s2 (after EB2).
//   - full[] barriers: cp.async.mbarrier.arrive.noinc; empty[]: plain arrive
//     after each thread's last read. All waits per-thread try_wait; NO
//     __syncthreads between first MMA and the final reduction.
//   - epilogue warp with row-strip wr waits ONLY on its own quarter (FBT wr).
// smem = 3*32768 + 16384 = 114688 -> 2 CTAs/SM (2*112 KB = 224 <= 228 KB).
// ---------------------------------------------------------------------------
#define SLOT_B   32768
#define STRIP    16384                     // A strip size within an op slot
#define T0_OFF   (3 * SLOT_B)              // 98304
#define SMEM_TOTAL (T0_OFF + 16384)        // 114688

#define LDSM4(R0, R1, R2, R3, ADDR)                                          \
    asm volatile("ldmatrix.sync.aligned.m8n8.x4.shared.b16 {%0,%1,%2,%3}, [%4];" \
                 : "=r"(R0), "=r"(R1), "=r"(R2), "=r"(R3) : "r"(ADDR))

#define MMA16816(C, A, B0, B1)                                               \
    asm volatile("mma.sync.aligned.m16n8k16.row.col.f32.bf16.bf16.f32 "      \
                 "{%0,%1,%2,%3}, {%4,%5,%6,%7}, {%8,%9}, {%0,%1,%2,%3};"     \
                 : "+f"((C)[0]), "+f"((C)[1]), "+f"((C)[2]), "+f"((C)[3])    \
                 : "r"((A)[0]), "r"((A)[1]), "r"((A)[2]), "r"((A)[3]),       \
                   "r"(B0), "r"(B1))

#define CP16(S, G)                                                           \
    asm volatile("cp.async.cg.shared.global [%0], [%1], 16;"                 \
                 :: "r"(S), "l"(G) : "memory")

#define ARRIVE_NOINC(MBAR)                                                   \
    asm volatile("cp.async.mbarrier.arrive.noinc.shared::cta.b64 [%0];"      \
                 :: "r"(MBAR) : "memory")

#define ARRIVE(MBAR)                                                         \
    asm volatile("mbarrier.arrive.shared::cta.b64 _, [%0];"                  \
                 :: "r"(MBAR) : "memory")

#define MBAR_WAIT_P0(MBAR) do {                                              \
    uint32_t _done;                                                          \
    asm volatile("{\n\t.reg .pred p;\n\t"                                    \
                 "mbarrier.try_wait.parity.acquire.cta.shared::cta.b64 p, [%1], 0;\n\t" \
                 "selp.b32 %0, 1, 0, p;\n\t}"                                \
                 : "=r"(_done) : "r"(MBAR) : "memory");                      \
    if (!_done) {                                                            \
        asm volatile("{\n\t.reg .pred P1;\n\t"                               \
                     "W%=:\n\t"                                              \
                     "mbarrier.try_wait.parity.acquire.cta.shared::cta.b64 P1, [%0], 0, 0x989680;\n\t" \
                     "@P1 bra.uni D%=;\n\t"                                  \
                     "bra.uni W%=;\n\t"                                      \
                     "D%=:\n\t}" :: "r"(MBAR) : "memory");                   \
    }                                                                        \
} while (0)

// Stage one K=64 operand chunk (A + B strips, swizzled 128 B rows) into slot.
__device__ __forceinline__ void stage_op(uint32_t slot, int ch,
                                         const char* Ag, const char* Bg,
                                         int tid) {
    #pragma unroll
    for (int i = tid; i < 1024; i += 256) {          // 128 rows x 8 x 16B
        const int r = i >> 3;
        const int c = i & 7;
        const uint32_t soff = (uint32_t)r * 128 + (uint32_t)((c ^ (r & 7)) << 4);
        const size_t   goff = (size_t)r * 512 + (size_t)ch * 128 + (size_t)c * 16;
        CP16(slot + soff, Ag + goff);
        CP16(slot + STRIP + soff, Bg + goff);
    }
}

// Stage 32 text rows (512 B each, swizzled 16B chunks) into a 16 KB region.
__device__ __forceinline__ void stage_textq(uint32_t dst, const char* tg,
                                            int B, int tid) {
    #pragma unroll
    for (int i = tid; i < 1024; i += 256) {          // 32 rows x 32 x 16B
        const int r = i >> 5;
        const int c = i & 31;
        const uint32_t soff = (uint32_t)r * 512 + (uint32_t)((c ^ (r & 7)) << 4);
        CP16(dst + soff, tg + (size_t)r * B * 4 + (size_t)c * 16);
    }
}

// One K=64 chunk of MMAs from the given slot (swizzled addressing).
__device__ __forceinline__ void mma_chunk(uint32_t slot, uint32_t aRow,
                                          uint32_t bRow, uint32_t aHi,
                                          uint32_t bHi, uint32_t s7,
                                          float c[2][8][4]) {
    #pragma unroll
    for (int kc = 0; kc < 4; kc++) {
        uint32_t a[2][4];
        #pragma unroll
        for (int mt = 0; mt < 2; mt++)
            LDSM4(a[mt][0], a[mt][1], a[mt][2], a[mt][3],
                  slot + aRow + (uint32_t)(mt * 2048)
                       + (uint32_t)((((kc * 2) + aHi) ^ s7) << 4));
        uint32_t b[4][4];
        #pragma unroll
        for (int p = 0; p < 4; p++)
            LDSM4(b[p][0], b[p][1], b[p][2], b[p][3],
                  slot + STRIP + bRow + (uint32_t)(p * 2048)
                       + (uint32_t)((((kc * 2) + bHi) ^ s7) << 4));
        #pragma unroll
        for (int mt = 0; mt < 2; mt++)
            #pragma unroll
            for (int nt = 0; nt < 8; nt++)
                MMA16816(c[mt][nt], a[mt],
                         b[nt >> 1][(nt & 1) * 2], b[nt >> 1][(nt & 1) * 2 + 1]);
    }
}

__global__ __launch_bounds__(256, 2)
void loss_kernel(const float* __restrict__ text, float* __restrict__ out,
                 int B, float scale) {
    extern __shared__ char smem[];
    uint32_t sbase;
    asm("{ .reg .u64 t; cvta.to.shared.u64 t, %1; cvt.u32.u64 %0, t; }"
        : "=r"(sbase) : "l"((const void*)smem));

    // barriers: FB0..FB3 (op chunks), FBT0..FBT3 (text quarters), EB0..EB2
    __shared__ __align__(8) uint64_t mbars[11];
    __shared__ float red[8];
    uint32_t mb0;
    asm("{ .reg .u64 t; cvta.to.shared.u64 t, %1; cvt.u32.u64 %0, t; }"
        : "=r"(mb0) : "l"((const void*)mbars));
    #define FB(i)  (mb0 + (i) * 8)          // op chunk i
    #define FBT(i) (mb0 + 32 + (i) * 8)     // text quarter i
    #define EB(i)  (mb0 + 64 + (i) * 8)     // empty, slot i

    const int tid = threadIdx.x;

    // ---- linear block id -> upper-triangular (by, bx), by <= bx ----
    const int NT = B >> 7;
    int t = blockIdx.x;
    int by = 0;
    while (t >= NT - by) { t -= NT - by; ++by; }
    const int bx = by + t;

    const char* __restrict__ Ag =
        reinterpret_cast<const char*>(g_en + (size_t)by * 32768);
    const char* __restrict__ Bg =
        reinterpret_cast<const char*>(g_en + (size_t)bx * 32768);
    const char* __restrict__ tg = reinterpret_cast<const char*>(
        text + (size_t)(by * 128) * B + (size_t)bx * 128);

    // ---- init barriers (all expect 256 arrivals) ----
    if (tid == 0) {
        #pragma unroll
        for (int m = 0; m < 11; m++)
            asm volatile("mbarrier.init.shared.b64 [%0], %1;"
                         :: "r"(mb0 + m * 8), "r"(256u) : "memory");
    }
    __syncthreads();   // init visible before any arrive

    const uint32_t s0 = sbase, s1 = sbase + SLOT_B, s2 = sbase + 2 * SLOT_B;
    const uint32_t t0 = sbase + T0_OFF;

    // ---- prologue: ch0->s0, ch1->s1, ch2->s2, text q0 -> T0 ----
    stage_op(s0, 0, Ag, Bg, tid);   ARRIVE_NOINC(FB(0));
    stage_op(s1, 1, Ag, Bg, tid);   ARRIVE_NOINC(FB(1));
    stage_op(s2, 2, Ag, Bg, tid);   ARRIVE_NOINC(FB(2));
    stage_textq(t0, tg, B, tid);    ARRIVE_NOINC(FBT(0));

    // ---- warp / fragment geometry ----
    const int warpId = tid >> 5;
    const int lane   = tid & 31;
    const int wr = warpId & 3;    // 32-row strip
    const int wc = warpId >> 2;   // 64-col strip
    const int grp = lane >> 3;

    const uint32_t aRow = (uint32_t)((wr * 32 + (lane & 15)) * 128);
    const uint32_t bRow = (uint32_t)((wc * 64 + (grp >> 1) * 8 + (lane & 7)) * 128);
    const uint32_t aHi  = (uint32_t)(lane >> 4);
    const uint32_t bHi  = (uint32_t)(grp & 1);
    const uint32_t s7   = (uint32_t)(lane & 7);

    float c[2][8][4];
    #pragma unroll
    for (int mt = 0; mt < 2; mt++)
        #pragma unroll
        for (int nt = 0; nt < 8; nt++)
            #pragma unroll
            for (int e = 0; e < 4; e++) c[mt][nt][e] = 0.0f;

    // ---- free-running pipeline (no __syncthreads until reduction) ----
    MBAR_WAIT_P0(FB(0));  mma_chunk(s0, aRow, bRow, aHi, bHi, s7, c);  ARRIVE(EB(0));
    MBAR_WAIT_P0(FB(1));  mma_chunk(s1, aRow, bRow, aHi, bHi, s7, c);  ARRIVE(EB(1));

    MBAR_WAIT_P0(EB(0));                       // all reads of ch0 done
    stage_op(s0, 3, Ag, Bg, tid);  ARRIVE_NOINC(FB(3));

    MBAR_WAIT_P0(FB(2));  mma_chunk(s2, aRow, bRow, aHi, bHi, s7, c);  ARRIVE(EB(2));

    MBAR_WAIT_P0(EB(1));                       // slot s1 free: q1 and q3
    stage_textq(s1, tg + (size_t)32 * B * 4, B, tid);          ARRIVE_NOINC(FBT(1));
    stage_textq(s1 + 16384, tg + (size_t)96 * B * 4, B, tid);  ARRIVE_NOINC(FBT(3));

    MBAR_WAIT_P0(EB(2));                       // slot s2 free: q2
    stage_textq(s2, tg + (size_t)64 * B * 4, B, tid);          ARRIVE_NOINC(FBT(2));

    MBAR_WAIT_P0(FB(3));  mma_chunk(s0, aRow, bRow, aHi, bHi, s7, c);

    // ---- epilogue: wait ONLY on this warp's text quarter ----
    MBAR_WAIT_P0(FBT(wr));

    const int qrow = lane >> 2;          // 0..7
    const int qcol = (lane & 3) * 2;     // 0,2,4,6
    const bool diag = (bx == by);
    // quarter bases: q0=T0, q1=s1, q2=s2, q3=s1+16K
    const uint32_t tq_off = (wr == 0) ? (uint32_t)T0_OFF
                         : (wr == 1) ? (uint32_t)SLOT_B
                         : (wr == 2) ? (uint32_t)(2 * SLOT_B)
                                     : (uint32_t)(SLOT_B + 16384);
    const char* __restrict__ Tb = smem + tq_off;

    float acc = 0.0f;
    #pragma unroll
    for (int mt = 0; mt < 2; mt++) {
        const int r0 = wr * 32 + mt * 16 + qrow;        // tile rows r0, r0+8
        const int lr = r0 & 31;                          // row within quarter
        #pragma unroll
        for (int nt = 0; nt < 8; nt++) {
            const int cc = wc * 64 + nt * 8 + qcol;
            const uint32_t chunk = (uint32_t)(cc >> 2);
            const uint32_t off = (uint32_t)lr * 512
                               + ((chunk ^ (uint32_t)qrow) << 4)
                               + (uint32_t)((cc & 3) * 4);
            const float2 t0v = *reinterpret_cast<const float2*>(Tb + off);
            const float2 t1v = *reinterpret_cast<const float2*>(Tb + off + 4096);
            const float* cf = c[mt][nt];
            if (!diag) {
                acc += fabsf(t0v.x - cf[0]) + fabsf(t0v.y - cf[1])
                     + fabsf(t1v.x - cf[2]) + fabsf(t1v.y - cf[3]);
            } else {
                if (cc     > r0)     acc += fabsf(t0v.x - cf[0]);
                if (cc + 1 > r0)     acc += fabsf(t0v.y - cf[1]);
                if (cc     > r0 + 8) acc += fabsf(t1v.x - cf[2]);
                if (cc + 1 > r0 + 8) acc += fabsf(t1v.y - cf[3]);
            }
        }
    }

    // ---- reduction: warp shuffle -> smem -> one atomicAdd ----
    #pragma unroll
    for (int o = 16; o > 0; o >>= 1) acc += __shfl_xor_sync(0xffffffffu, acc, o);
    if (lane == 0) red[warpId] = acc;
    __syncthreads();
    if (tid == 0) {
        float s = 0.0f;
        #pragma unroll
        for (int w = 0; w < 8; w++) s += red[w];
        atomicAdd(out, s * scale);
    }
}

// ---------------------------------------------------------------------------
// Launch
// ---------------------------------------------------------------------------
extern "C" void kernel_launch(void* const* d_in, const int* in_sizes, int n_in,
                              void* d_out, int out_size) {
    const float* emb  = (const float*)d_in[0];   // [B, D] fp32
    const float* text = (const float*)d_in[1];   // [B, B] fp32
    float* out = (float*)d_out;

    const int B = (int)(sqrt((double)in_sizes[1]) + 0.5);   // 8192
    const double count = (double)B * (double)(B - 1) / 2.0;
    const float scale = (float)(0.1 / count);

    cudaFuncSetAttribute(loss_kernel,
                         cudaFuncAttributeMaxDynamicSharedMemorySize, SMEM_TOTAL);

    normalize_kernel<<<B / 8, 256>>>(emb, B, out);

    const int NT = B / 128;
    const int nblocks = NT * (NT + 1) / 2;   // 2080 upper-tri tiles
    loss_kernel<<<nblocks, 256, SMEM_TOTAL>>>(text, out, B, scale);
}